// round 6
// baseline (speedup 1.0000x reference)
#include <cuda_runtime.h>
#include <stdint.h>

#define H 2048
#define W 2048
#define KS 11
#define PS 10
#define PAD 5
#define HO 205                 // conv output: floor((2048+10-11)/10)+1
#define OUT 2255               // 205 * (PS+1)
#define CELLS (HO*HO)
#define ROWS_TOTAL (3*OUT)
#define TS_W 88                // smem tile width (floats); 81 used

// Intermediate per-cell result: [3][HO][HO] (+pad for safe over-read)
__device__ float g_mid[3 * HO * HO + 8];

// ---------------------------------------------------------------------------
// Kernel 1: 8 warps per block = 8 adjacent cells (same oh, ow0..ow0+7).
// Cooperative coalesced load of the 11 x 81 union window into smem, then
// per-warp: 16-bin histogram (packed 8-bit counters), argmax via one
// reduce-max (first-max tie-break like jnp.argmax), masked channel means.
// ---------------------------------------------------------------------------
__global__ void __launch_bounds__(256) cell_kernel(const float* __restrict__ rgb) {
    __shared__ float tile[3][11][TS_W];

    const int oh  = blockIdx.y;
    const int ow0 = blockIdx.x * 8;
    const int wid = threadIdx.x >> 5;
    const int lane = threadIdx.x & 31;
    const int y0b = oh * PS - PAD;
    const int x0b = ow0 * PS - PAD;

    // Cooperative load: 33 strips (ch,row) of 88 px, coalesced.
    for (int s = wid; s < 33; s += 8) {
        const int ch  = (s >= 22) ? 2 : ((s >= 11) ? 1 : 0);
        const int row = s - ch * 11;
        const int gy  = y0b + row;                 // max 2045 < 2048 always
        const bool yok = (gy >= 0);
        const float* __restrict__ src = rgb + ch * (H * W) + gy * W + x0b;
#pragma unroll
        for (int u = 0; u < 3; u++) {
            const int col = lane + u * 32;
            if (col < TS_W) {
                const int gx = x0b + col;
                float v = 0.0f;
                if (yok && gx >= 0 && gx < W) v = __ldg(src + col);
                tile[ch][row][col] = v;
            }
        }
    }
    __syncthreads();

    const int ow = ow0 + wid;
    if (ow >= HO) return;
    const int y0 = y0b;
    const int x0 = ow * PS - PAD;

    // p = lane + 32t; window is 121 px: t=0..2 active, t=3 iff lane<25.
    int dyc[4], col[4];
    bool act[4];
    act[0] = true; act[1] = true; act[2] = true; act[3] = (lane < 25);
#pragma unroll
    for (int t = 0; t < 4; t++) {
        const int p = lane + t * 32;
        int dy = p / KS;                          // <= 11 (p=127)
        const int dx = p - dy * KS;
        if (dy > 10) dy = 10;                     // clamp smem addr; act=false
        dyc[t] = dy;
        col[t] = wid * 10 + dx;
    }
    if ((oh == 0) | (ow == 0)) {                  // border cells: 409 of 42025
#pragma unroll
        for (int t = 0; t < 4; t++) {
            const int p = lane + t * 32;
            const int dy = p / KS;
            const int dx = p - dy * KS;
            act[t] = act[t] && (y0 + dy >= 0) && (x0 + dx >= 0);
        }
    }

    float rv[4], gv[4], bv[4];
#pragma unroll
    for (int t = 0; t < 4; t++) rv[t] = act[t] ? tile[0][dyc[t]][col[t]] : 0.0f;
#pragma unroll
    for (int t = 0; t < 4; t++) gv[t] = act[t] ? tile[1][dyc[t]][col[t]] : 0.0f;
#pragma unroll
    for (int t = 0; t < 4; t++) bv[t] = act[t] ? tile[2][dyc[t]][col[t]] : 0.0f;

    // Bin + packed histogram (bins 0-7 in hlo, 8-15 in hhi; 8-bit counters,
    // per-bin totals <= 121 < 256 so the warp reduction is carry-free)
    int bn[4];
    unsigned long long hlo = 0ULL, hhi = 0ULL;
#pragma unroll
    for (int t = 0; t < 4; t++) {
        // bin = floor(mean(r,g,b)/256*16) = floor((r+g+b)*(1/3)*2^-4)
        const float s = __fadd_rn(__fadd_rn(rv[t], gv[t]), bv[t]);
        const float m = __fmul_rn(s, 0.3333333432674408f);   // 1/3 rn
        const int bi = (int)(__fmul_rn(m, 0.0625f));          // in [0,15]
        bn[t] = bi;
        if (act[t]) {
            const unsigned long long inc = 1ULL << ((bi & 7) * 8);
            if (bi < 8) hlo += inc; else hhi += inc;
        }
    }

    const unsigned h0 = __reduce_add_sync(0xffffffffu, (unsigned)hlo);
    const unsigned h1 = __reduce_add_sync(0xffffffffu, (unsigned)(hlo >> 32));
    const unsigned h2 = __reduce_add_sync(0xffffffffu, (unsigned)hhi);
    const unsigned h3 = __reduce_add_sync(0xffffffffu, (unsigned)(hhi >> 32));

    // Lane-parallel argmax: lane (b = lane&15) owns bin b.
    // key = (cnt<<4) | (15-b): ties -> smaller bin wins (jnp.argmax).
    const int b = lane & 15;
    const unsigned hw = (b < 8) ? ((b < 4) ? h0 : h1) : ((b < 12) ? h2 : h3);
    const unsigned cnt = (hw >> ((b & 3) * 8)) & 0xFFu;
    const unsigned key = (cnt << 4) | (unsigned)(15 - b);
    const unsigned kmax = __reduce_max_sync(0xffffffffu, key);
    const int amax = 15 - (int)(kmax & 15u);
    const float cm = (float)(kmax >> 4);

    // Masked per-channel sums (inactive slots hold 0.0)
    float sr = 0.f, sg = 0.f, sb = 0.f;
#pragma unroll
    for (int t = 0; t < 4; t++) {
        if (bn[t] == amax) { sr += rv[t]; sg += gv[t]; sb += bv[t]; }
    }
#pragma unroll
    for (int s = 16; s > 0; s >>= 1) {
        sr += __shfl_xor_sync(0xffffffffu, sr, s);
        sg += __shfl_xor_sync(0xffffffffu, sg, s);
        sb += __shfl_xor_sync(0xffffffffu, sb, s);
    }

    if (lane == 0) {
        const float inv = __frcp_rn(cm);
        const int idx = oh * HO + ow;
        g_mid[idx]               = __fmul_rn(sr, inv);
        g_mid[idx + HO * HO]     = __fmul_rn(sg, inv);
        g_mid[idx + 2 * HO * HO] = __fmul_rn(sb, inv);
    }
}

// ---------------------------------------------------------------------------
// Kernel 2: upsample 205x205 -> 2255x2255 per channel.
// One block per output row; float4 stores; incremental (ow,j) tracking
// (x advances by 512 = 46*11 + 6 per iteration -> no per-element division).
// ---------------------------------------------------------------------------
__global__ void __launch_bounds__(128) upsample_kernel(float* __restrict__ out,
                                                       int rbase) {
    const int row = rbase + blockIdx.x;    // 0 .. 3*2255-1
    const int tid = threadIdx.x;
    const unsigned ur = (unsigned)row;
    const unsigned c = ur / (unsigned)OUT;
    const unsigned y = ur - c * (unsigned)OUT;
    const unsigned oh = y / 11u;
    const unsigned ii = y - oh * 11u;

    float* __restrict__ orow = out + (size_t)row * OUT;
    const int h = (int)((4u - ((ur * (unsigned)OUT) & 3u)) & 3u);
    const int nv = (OUT - h) >> 2;
    const int nt = OUT - h - nv * 4;
    float4* __restrict__ ov = (float4*)(orow + h);

    if (ii == 10u) {                       // pad row: zeros
        if (tid < h) orow[tid] = 0.0f;
        if (tid >= 4 && tid < 4 + nt) orow[h + nv * 4 + (tid - 4)] = 0.0f;
        const float4 z = make_float4(0.f, 0.f, 0.f, 0.f);
        for (int v = tid; v < nv; v += 128) ov[v] = z;
        return;
    }

    const float* __restrict__ midc = g_mid + c * HO * HO + oh * HO;

    // Scalar head (x <= 2: o=0, j<10 -> always live)
    if (tid < h) orow[tid] = __ldg(midc);
    // Scalar tail (x in 2252..2254)
    if (tid >= 4 && tid < 4 + nt) {
        const unsigned x = (unsigned)(h + nv * 4 + (tid - 4));
        const unsigned o = x / 11u;
        const unsigned j = x - o * 11u;
        orow[x] = (j < 10u) ? __ldg(midc + o) : 0.0f;
    }

    // Vector body: one division up front, then incremental carry.
    unsigned x = (unsigned)(h + 4 * tid);
    unsigned ow = x / 11u;
    int j = (int)(x - ow * 11u);
    for (int v = tid; v < nv; v += 128) {
        const float m0 = __ldg(midc + ow);
        const float m1 = __ldg(midc + ow + 1);   // padded; unused if j+k<=10
        float4 o;
        o.x = (j     < 10) ? m0 : ((j     == 10) ? 0.0f : m1);
        o.y = (j + 1 < 10) ? m0 : ((j + 1 == 10) ? 0.0f : m1);
        o.z = (j + 2 < 10) ? m0 : ((j + 2 == 10) ? 0.0f : m1);
        o.w = (j + 3 < 10) ? m0 : ((j + 3 == 10) ? 0.0f : m1);
        ov[v] = o;
        ow += 46u; j += 6;                       // x += 512 = 46*11 + 6
        if (j >= 11) { j -= 11; ow += 1u; }
    }
}

extern "C" void kernel_launch(void* const* d_in, const int* in_sizes, int n_in,
                              void* d_out, int out_size) {
    const float* rgb = (const float*)d_in[0];
    float* out = (float*)d_out;

    dim3 cgrid((HO + 7) / 8, HO);              // 26 x 205 blocks, 8 cells each
    cell_kernel<<<cgrid, 256>>>(rgb);

    const int half = ROWS_TOTAL / 2;           // 3382
    upsample_kernel<<<half, 128>>>(out, 0);
    upsample_kernel<<<ROWS_TOTAL - half, 128>>>(out, half);
}

// round 7
// speedup vs baseline: 1.3067x; 1.3067x over previous
#include <cuda_runtime.h>
#include <stdint.h>

#define H 2048
#define W 2048
#define KS 11
#define PS 10
#define PAD 5
#define HO 205                 // conv output: floor((2048+10-11)/10)+1
#define OUT 2255               // 205 * (PS+1)
#define CELLS (HO*HO)
#define ROWS_TOTAL (3*OUT)

// Intermediate per-cell result: [3][HO][HO] (+pad for safe over-read)
__device__ float g_mid[3 * HO * HO + 8];

// ---------------------------------------------------------------------------
// Kernel 1: one warp per output cell (direct LDG version — fastest measured).
// 16-bin histogram of the 11x11 window (packed 8-bit counters), argmax bin
// via single warp-reduce-max (first-max tie-break like jnp.argmax),
// per-channel mean of pixels in that bin.
// ---------------------------------------------------------------------------
__global__ void __launch_bounds__(256) cell_kernel(const float* __restrict__ rgb) {
    const int wid = (blockIdx.x * blockDim.x + threadIdx.x) >> 5;
    if (wid >= CELLS) return;
    const int lane = threadIdx.x & 31;

    const int oh = wid / HO;
    const int ow = wid - oh * HO;
    const int y0 = oh * PS - PAD;
    const int x0 = ow * PS - PAD;

    const float* __restrict__ rp = rgb;
    const float* __restrict__ gp = rgb + H * W;
    const float* __restrict__ bp = rgb + 2 * H * W;

    // p = lane + 32t; window is 121 px: t=0..2 always active, t=3 iff lane<25.
    int off[4];
    bool act[4];
    act[0] = true; act[1] = true; act[2] = true; act[3] = (lane < 25);
#pragma unroll
    for (int t = 0; t < 4; t++) {
        const int p = lane + t * 32;
        const int dy = p / KS;
        const int dx = p - dy * KS;
        off[t] = (y0 + dy) * W + (x0 + dx);
    }
    if ((oh == 0) | (ow == 0)) {   // border cells: 409 of 42025
#pragma unroll
        for (int t = 0; t < 4; t++) {
            const int p = lane + t * 32;
            const int dy = p / KS;
            const int dx = p - dy * KS;
            act[t] = act[t] && (y0 + dy >= 0) && (x0 + dx >= 0);
        }
    }

    // Batch all loads first (max MLP); inactive slots hold 0.
    float rv[4], gv[4], bv[4];
#pragma unroll
    for (int t = 0; t < 4; t++) rv[t] = act[t] ? __ldg(rp + off[t]) : 0.0f;
#pragma unroll
    for (int t = 0; t < 4; t++) gv[t] = act[t] ? __ldg(gp + off[t]) : 0.0f;
#pragma unroll
    for (int t = 0; t < 4; t++) bv[t] = act[t] ? __ldg(bp + off[t]) : 0.0f;

    // Bin + packed histogram (bins 0-7 in hlo, 8-15 in hhi; 8-bit counters,
    // per-bin totals <= 121 < 256 so the warp reduction is carry-free)
    int bn[4];
    unsigned long long hlo = 0ULL, hhi = 0ULL;
#pragma unroll
    for (int t = 0; t < 4; t++) {
        // bin = floor(mean(r,g,b)/256*16) = floor((r+g+b)*(1/3)*2^-4)
        const float s = __fadd_rn(__fadd_rn(rv[t], gv[t]), bv[t]);
        const float m = __fmul_rn(s, 0.3333333432674408f);   // 1/3 rn
        const int bi = (int)(__fmul_rn(m, 0.0625f));          // in [0,15]
        bn[t] = bi;
        if (act[t]) {
            const unsigned long long inc = 1ULL << ((bi & 7) * 8);
            if (bi < 8) hlo += inc; else hhi += inc;
        }
    }

    const unsigned h0 = __reduce_add_sync(0xffffffffu, (unsigned)hlo);
    const unsigned h1 = __reduce_add_sync(0xffffffffu, (unsigned)(hlo >> 32));
    const unsigned h2 = __reduce_add_sync(0xffffffffu, (unsigned)hhi);
    const unsigned h3 = __reduce_add_sync(0xffffffffu, (unsigned)(hhi >> 32));

    // Lane-parallel argmax: lane (b = lane&15) owns bin b.
    // key = (cnt<<4) | (15-b): ties -> smaller bin wins (jnp.argmax).
    const int b = lane & 15;
    const unsigned hw = (b < 8) ? ((b < 4) ? h0 : h1) : ((b < 12) ? h2 : h3);
    const unsigned cnt = (hw >> ((b & 3) * 8)) & 0xFFu;
    const unsigned key = (cnt << 4) | (unsigned)(15 - b);
    const unsigned kmax = __reduce_max_sync(0xffffffffu, key);
    const int amax = 15 - (int)(kmax & 15u);
    const float cm = (float)(kmax >> 4);

    // Masked per-channel sums (inactive slots hold 0.0)
    float sr = 0.f, sg = 0.f, sb = 0.f;
#pragma unroll
    for (int t = 0; t < 4; t++) {
        if (bn[t] == amax) { sr += rv[t]; sg += gv[t]; sb += bv[t]; }
    }
#pragma unroll
    for (int s = 16; s > 0; s >>= 1) {
        sr += __shfl_xor_sync(0xffffffffu, sr, s);
        sg += __shfl_xor_sync(0xffffffffu, sg, s);
        sb += __shfl_xor_sync(0xffffffffu, sb, s);
    }

    if (lane == 0) {
        const float inv = __frcp_rn(cm);
        g_mid[wid]               = __fmul_rn(sr, inv);
        g_mid[wid + HO * HO]     = __fmul_rn(sg, inv);
        g_mid[wid + 2 * HO * HO] = __fmul_rn(sb, inv);
    }
}

// ---------------------------------------------------------------------------
// Kernel 2: upsample 205x205 -> 2255x2255 per channel.
// One block (576 threads) per output row, ONE float4 per thread — no serial
// loop, so the LDG->select->STG dependency chain is hidden by sheer thread
// parallelism. Head/tail scalars handled by dedicated high tids.
// ---------------------------------------------------------------------------
__global__ void __launch_bounds__(576) upsample_kernel(float* __restrict__ out) {
    const int row = blockIdx.x;            // 0 .. 3*2255-1
    const int tid = threadIdx.x;
    const unsigned ur = (unsigned)row;
    const unsigned c = ur / (unsigned)OUT;
    const unsigned y = ur - c * (unsigned)OUT;
    const unsigned oh = y / 11u;
    const unsigned ii = y - oh * 11u;
    const bool live = (ii != 10u);

    float* __restrict__ orow = out + (size_t)row * OUT;
    const int h = (int)((4u - ((ur * (unsigned)OUT) & 3u)) & 3u);
    const int nv = (OUT - h) >> 2;         // 563
    const int nt = OUT - h - nv * 4;       // 0..3

    const float* __restrict__ midc = g_mid + c * (HO * HO) + oh * HO;

    if (tid < nv) {
        const unsigned x = (unsigned)(h + 4 * tid);
        const unsigned ow = x / 11u;
        const int j = (int)(x - ow * 11u);
        float4 o;
        if (live) {
            const float m0 = __ldg(midc + ow);
            const float m1 = __ldg(midc + ow + 1);   // padded; unused if j+3<=9
            o.x = (j     < 10) ? m0 : ((j     == 10) ? 0.0f : m1);
            o.y = (j + 1 < 10) ? m0 : ((j + 1 == 10) ? 0.0f : m1);
            o.z = (j + 2 < 10) ? m0 : ((j + 2 == 10) ? 0.0f : m1);
            o.w = (j + 3 < 10) ? m0 : ((j + 3 == 10) ? 0.0f : m1);
        } else {
            o = make_float4(0.f, 0.f, 0.f, 0.f);
        }
        *(float4*)(orow + h + 4 * tid) = o;
    } else if (tid >= 570 && tid < 573) {
        // Head: x = 0..h-1 (<=2): ow=0, j<10 -> live value
        const int x = tid - 570;
        if (x < h) orow[x] = live ? __ldg(midc) : 0.0f;
    } else if (tid >= 573) {
        // Tail: x in [h+4*nv, OUT): x >= 2252, ow=204, j = x-2244
        const int x = h + 4 * nv + (tid - 573);
        if (x < OUT) {
            const int j = x - 2244;
            orow[x] = (live && j < 10) ? __ldg(midc + 204) : 0.0f;
        }
    }
}

extern "C" void kernel_launch(void* const* d_in, const int* in_sizes, int n_in,
                              void* d_out, int out_size) {
    const float* rgb = (const float*)d_in[0];
    float* out = (float*)d_out;

    const int blocks1 = (CELLS + 7) / 8;       // one warp per cell, 8/block
    cell_kernel<<<blocks1, 256>>>(rgb);

    upsample_kernel<<<ROWS_TOTAL, 576>>>(out); // one block per output row
}